// round 6
// baseline (speedup 1.0000x reference)
#include <cuda_runtime.h>
#include <cstdint>

// predictions [8,19,512,1024] f32, targets [8,512,1024] i32, output: scalar f32.
#define NB        8
#define NC        19
#define NPB       (512 * 1024)
#define LOG2_NPB  19
#define THRESH    0.7f
#define NMIN      10000

#define TPB       256
#define TILE      512                      // pixels per tile
#define CH_BYTES  (TILE * 4)               // 2048 B per channel chunk
#define TILE_BYTES ((NC + 1) * CH_BYTES)   // 19 channels + targets = 40960 B
#define TILE_FLOATS (TILE_BYTES / 4)
#define STAGES    2
#define NTILES    ((NB * NPB) / TILE)      // 16384
#define GRID      296                      // 2 blocks/SM * 148 SMs

__device__ double       g_sum[NB];
__device__ int          g_cnt[NB];
__device__ unsigned int g_done;

// ---------------- PTX helpers ----------------
__device__ __forceinline__ uint32_t smem_u32(const void* p) {
    uint32_t a;
    asm("{ .reg .u64 t; cvta.to.shared.u64 t, %1; cvt.u32.u64 %0, t; }"
        : "=r"(a) : "l"(p));
    return a;
}
#define MBAR_INIT(addr, cnt) \
    asm volatile("mbarrier.init.shared.b64 [%0], %1;" :: "r"(addr), "r"(cnt) : "memory")
#define MBAR_EXPECT_TX(addr, bytes) \
    asm volatile("mbarrier.arrive.expect_tx.shared.b64 _, [%0], %1;" :: "r"(addr), "r"(bytes) : "memory")
#define MBAR_ARRIVE(addr) \
    asm volatile("mbarrier.arrive.shared.b64 _, [%0];" :: "r"(addr) : "memory")
#define MBAR_WAIT(addr, parity) do {                                              \
    asm volatile("{\n\t.reg .pred P;\n"                                           \
                 "W_%=:\n\t"                                                      \
                 "mbarrier.try_wait.parity.acquire.cta.shared::cta.b64 P, [%0], %1, 0x989680;\n\t" \
                 "@P bra D_%=;\n\t"                                               \
                 "bra W_%=;\n"                                                    \
                 "D_%=:\n\t}"                                                     \
                 :: "r"(addr), "r"(parity) : "memory");                           \
} while (0)
#define TMA_BULK_G2S(dst, src, bytes, mbar) \
    asm volatile("cp.async.bulk.shared::cta.global.mbarrier::complete_tx::bytes [%0], [%1], %2, [%3];" \
                 :: "r"(dst), "l"(src), "r"(bytes), "r"(mbar) : "memory")

// CE loss recompute (rare exact-top-k fallback path only).
__device__ __forceinline__ float pixel_loss(const float* __restrict__ pred,
                                            const int*   __restrict__ tgt,
                                            int b, int i) {
    const int t = tgt[b * NPB + i];
    float s = 0.f, xt = 0.f;
#pragma unroll
    for (int c = 0; c < NC; c++) {
        const float v = pred[(b * NC + c) * NPB + i];
        s += __expf(v);
        if (c == t) xt = v;
    }
    float l = __logf(s) - xt;
    return l < 0.f ? 0.f : l;
}

extern __shared__ float sbuf[];   // STAGES * TILE_FLOATS

__global__ void __launch_bounds__(TPB)
ohem_tma(const float* __restrict__ pred,
         const int*   __restrict__ tgt,
         float*       __restrict__ out) {
    __shared__ __align__(8) uint64_t mbar[STAGES * 2];   // [full0,full1,empty0,empty1]
    __shared__ float        sh_f[TPB / 32];
    __shared__ int          sh_i[TPB / 32];
    __shared__ unsigned int sh_last;

    const int tid  = threadIdx.x;
    const int w    = tid >> 5, lane = tid & 31;
    const uint32_t mb = smem_u32(mbar);
    const uint32_t sb = smem_u32(sbuf);

    if (tid == 0) {
#pragma unroll
        for (int s = 0; s < STAGES; s++) {
            MBAR_INIT(mb + s * 8, 1);                    // full: 1 expect_tx arrive
            MBAR_INIT(mb + (STAGES + s) * 8, TPB);       // empty: all consumers
        }
    }
    __syncthreads();

    const int ntiles_mine = (NTILES - blockIdx.x + GRID - 1) / GRID;

    int prod_stage = 0, prod_phase = 1;   // phase=1: first empty-wait passes
    int cons_stage = 0, cons_phase = 0;
    int produced = 0;

    for (int k = 0; k < ntiles_mine; k++) {
        // -------- producer (thread 0): keep up to STAGES tiles in flight ----
        if (tid == 0) {
            while (produced < ntiles_mine && produced < k + STAGES) {
                const int  tile = blockIdx.x + produced * GRID;
                const int  pix0 = tile * TILE;
                const int  b    = pix0 >> LOG2_NPB;
                const int  n    = pix0 & (NPB - 1);
                const uint32_t full  = mb + prod_stage * 8;
                const uint32_t empty = mb + (STAGES + prod_stage) * 8;
                MBAR_WAIT(empty, prod_phase);
                MBAR_EXPECT_TX(full, TILE_BYTES);
                const uint32_t dst0 = sb + prod_stage * TILE_BYTES;
                const char* srcb = (const char*)(pred + ((size_t)b * NC) * NPB + n);
#pragma unroll
                for (int c = 0; c < NC; c++)
                    TMA_BULK_G2S(dst0 + c * CH_BYTES,
                                 srcb + (size_t)c * NPB * 4, CH_BYTES, full);
                TMA_BULK_G2S(dst0 + NC * CH_BYTES,
                             (const char*)(tgt + pix0), CH_BYTES, full);
                produced++;
                if (++prod_stage == STAGES) { prod_stage = 0; prod_phase ^= 1; }
            }
        }

        // -------- consumer: all threads -----------------------------------
        const uint32_t full  = mb + cons_stage * 8;
        const uint32_t empty = mb + (STAGES + cons_stage) * 8;
        MBAR_WAIT(full, cons_phase);

        const float* buf = sbuf + cons_stage * (TILE_BYTES / 4);
        const int p = tid * 2;                    // 2 pixels per thread

        float s0 = 0.f, s1 = 0.f;
#pragma unroll
        for (int c = 0; c < NC; c++) {
            const float2 v = *reinterpret_cast<const float2*>(buf + c * TILE + p);
            s0 += __expf(v.x);
            s1 += __expf(v.y);
        }
        const int2 tt = *reinterpret_cast<const int2*>(
            reinterpret_cast<const int*>(buf + NC * TILE) + p);
        const float x0 = buf[tt.x * TILE + p];
        const float x1 = buf[tt.y * TILE + p + 1];
        const float l0 = __logf(s0) - x0;
        const float l1 = __logf(s1) - x1;

        MBAR_ARRIVE(empty);
        if (++cons_stage == STAGES) { cons_stage = 0; cons_phase ^= 1; }

        float ls = 0.f;
        int   lc = 0;
        if (l0 > THRESH) { ls += l0; lc++; }
        if (l1 > THRESH) { ls += l1; lc++; }
#pragma unroll
        for (int o = 16; o; o >>= 1) {
            ls += __shfl_down_sync(0xffffffffu, ls, o);
            lc += __shfl_down_sync(0xffffffffu, lc, o);
        }
        if (lane == 0) { sh_f[w] = ls; sh_i[w] = lc; }
        __syncthreads();
        if (tid == 0) {
            double S = 0.0; int Cn = 0;
#pragma unroll
            for (int i = 0; i < TPB / 32; i++) { S += (double)sh_f[i]; Cn += sh_i[i]; }
            const int tile = blockIdx.x + k * GRID;
            const int b    = tile >> (LOG2_NPB - 9);   // TILE = 2^9
            atomicAdd(&g_sum[b], S);
            atomicAdd(&g_cnt[b], Cn);
        }
        __syncthreads();   // protect sh_f/sh_i reuse next tile
    }

    // ---------------- done ticket + finalize (last block) ------------------
    if (tid == 0) {
        __threadfence();
        const unsigned int tk = atomicAdd(&g_done, 1u);
        sh_last = (tk == (unsigned)(GRID - 1)) ? 1u : 0u;
    }
    __syncthreads();
    if (!sh_last) return;
    __threadfence();

    __shared__ unsigned int hist[256];
    __shared__ unsigned int s_prefix;
    __shared__ int          s_k;
    __shared__ double       sh_d2[TPB / 32];
    __shared__ int          sh_i2[TPB / 32];
    __shared__ double       s_acc;

    if (tid == 0) s_acc = 0.0;
    __syncthreads();

    for (int bb = 0; bb < NB; bb++) {
        const int    cnt = g_cnt[bb];
        const double sum = g_sum[bb];

        if (cnt >= NMIN) {
            if (tid == 0) s_acc += sum / (double)cnt;
            __syncthreads();
        } else {
            // Exact top-NMIN via 4-pass MSB radix select (dead on this input).
            if (tid == 0) { s_prefix = 0u; s_k = NMIN; }
            __syncthreads();
            for (int pass = 0; pass < 4; pass++) {
                const int shift = 24 - pass * 8;
                for (int i = tid; i < 256; i += TPB) hist[i] = 0u;
                __syncthreads();
                const unsigned prefix  = s_prefix;
                const unsigned mask_hi = (pass == 0) ? 0u
                                       : (0xFFFFFFFFu << (shift + 8));
                for (int i = tid; i < NPB; i += TPB) {
                    const unsigned u = __float_as_uint(pixel_loss(pred, tgt, bb, i));
                    if ((u & mask_hi) == prefix)
                        atomicAdd(&hist[(u >> shift) & 255u], 1u);
                }
                __syncthreads();
                if (tid == 0) {
                    int kk = s_k;
                    int d  = 255;
                    while (d > 0 && (int)hist[d] < kk) { kk -= (int)hist[d]; d--; }
                    s_prefix = prefix | ((unsigned)d << shift);
                    s_k      = kk;
                }
                __syncthreads();
            }
            const float pivot = __uint_as_float(s_prefix);
            double fs = 0.0; int fg = 0;
            for (int i = tid; i < NPB; i += TPB) {
                const float vv = pixel_loss(pred, tgt, bb, i);
                if (vv > pivot) { fs += (double)vv; fg++; }
            }
#pragma unroll
            for (int o = 16; o; o >>= 1) {
                fs += __shfl_down_sync(0xffffffffu, fs, o);
                fg += __shfl_down_sync(0xffffffffu, fg, o);
            }
            if (lane == 0) { sh_d2[w] = fs; sh_i2[w] = fg; }
            __syncthreads();
            if (tid == 0) {
                double S = 0.0; int G = 0;
#pragma unroll
                for (int i = 0; i < TPB / 32; i++) { S += sh_d2[i]; G += sh_i2[i]; }
                const double kept = S + (double)(NMIN - G) * (double)pivot;
                s_acc += kept / (double)NMIN;
            }
            __syncthreads();
        }
    }

    if (tid == 0) {
        out[0] = (float)(s_acc / (double)NB);
#pragma unroll
        for (int i = 0; i < NB; i++) { g_sum[i] = 0.0; g_cnt[i] = 0; }
        g_done = 0u;
        __threadfence();
    }
}

extern "C" void kernel_launch(void* const* d_in, const int* in_sizes, int n_in,
                              void* d_out, int out_size) {
    const float* pred = (const float*)d_in[0];
    const int*   tgt  = (const int*)d_in[1];
    float*       out  = (float*)d_out;

    static int smem_set = 0;
    if (!smem_set) {
        cudaFuncSetAttribute(ohem_tma,
                             cudaFuncAttributeMaxDynamicSharedMemorySize,
                             STAGES * TILE_BYTES);
        smem_set = 1;
    }
    ohem_tma<<<GRID, TPB, STAGES * TILE_BYTES>>>(pred, tgt, out);
}

// round 7
// speedup vs baseline: 1.2182x; 1.2182x over previous
#include <cuda_runtime.h>
#include <cstdint>

// predictions [8,19,512,1024] f32, targets [8,512,1024] i32, output: scalar f32.
#define NB        8
#define NC        19
#define NPB       (512 * 1024)
#define THRESH    0.7f
#define NMIN      10000

#define TPB       256
#define TILE      512                          // pixels per tile
#define CH_BYTES  (TILE * 4)                   // 2048 B per channel chunk
#define TILE_BYTES ((NC + 1) * CH_BYTES)       // 19 ch + targets = 40960 B
#define CHUNKS    (TILE_BYTES / 16)            // 2560 x 16B chunks per tile
#define CPT       (CHUNKS / TPB)               // 10 chunks per thread
#define STAGES    2
#define TILES_PER_BATCH (NPB / TILE)           // 2048
#define BLK_PER_BATCH   37
#define GRID      (NB * BLK_PER_BATCH)         // 296

__device__ double       g_sum[NB];
__device__ int          g_cnt[NB];
__device__ unsigned int g_done;

// ---------------- PTX helpers ----------------
__device__ __forceinline__ uint32_t smem_u32(const void* p) {
    uint32_t a;
    asm("{ .reg .u64 t; cvta.to.shared.u64 t, %1; cvt.u32.u64 %0, t; }"
        : "=r"(a) : "l"(p));
    return a;
}
__device__ __forceinline__ void cp16(uint32_t dst, const void* src) {
    asm volatile("cp.async.cg.shared.global [%0], [%1], 16;"
                 :: "r"(dst), "l"(src) : "memory");
}
__device__ __forceinline__ void cp_commit() {
    asm volatile("cp.async.commit_group;" ::: "memory");
}
template <int N>
__device__ __forceinline__ void cp_wait() {
    asm volatile("cp.async.wait_group %0;" :: "n"(N) : "memory");
}

// CE loss recompute (rare exact-top-k fallback path only).
__device__ __forceinline__ float pixel_loss(const float* __restrict__ pred,
                                            const int*   __restrict__ tgt,
                                            int b, int i) {
    const int t = tgt[b * NPB + i];
    float s = 0.f, xt = 0.f;
#pragma unroll
    for (int c = 0; c < NC; c++) {
        const float v = pred[(b * NC + c) * NPB + i];
        s += __expf(v);
        if (c == t) xt = v;
    }
    float l = __logf(s) - xt;
    return l < 0.f ? 0.f : l;
}

extern __shared__ float sbuf[];   // STAGES * TILE_BYTES/4, 16B aligned

// Distributed fill of one stage with one tile (all 256 threads, 10 chunks each).
__device__ __forceinline__ void fill_tile(const float* __restrict__ pred,
                                          const int*   __restrict__ tgt,
                                          uint32_t sb, int stage,
                                          int b, int n /*pixel offset in batch*/,
                                          int tid) {
    const uint32_t dst0 = sb + stage * TILE_BYTES;
    const char* pbase = (const char*)(pred + (size_t)b * NC * NPB + n);
    const char* tbase = (const char*)(tgt + (size_t)b * NPB + n);
#pragma unroll
    for (int i = 0; i < CPT; i++) {
        const int j   = tid + i * TPB;          // chunk id 0..2559
        const int c   = j >> 7;                 // 16 chunks... j/128: channel row
        const int off = (j & 127) * 16;         // byte offset within 2KB row
        const char* src = (c < NC) ? (pbase + (size_t)c * NPB * 4 + off)
                                   : (tbase + off);
        cp16(dst0 + j * 16, src);
    }
    cp_commit();
}

__global__ void __launch_bounds__(TPB)
ohem_cpa(const float* __restrict__ pred,
         const int*   __restrict__ tgt,
         float*       __restrict__ out) {
    __shared__ float        sh_f[TPB / 32];
    __shared__ int          sh_i[TPB / 32];
    __shared__ unsigned int sh_last;

    const int tid  = threadIdx.x;
    const int w    = tid >> 5, lane = tid & 31;
    const uint32_t sb = smem_u32(sbuf);

    // Block -> (batch, local block index). 296 = 8 * 37, so batch is constant
    // per block and per-thread accumulators never mix batches.
    const int b  = blockIdx.x / BLK_PER_BATCH;
    const int jb = blockIdx.x % BLK_PER_BATCH;
    const int ntiles = (TILES_PER_BATCH - jb + BLK_PER_BATCH - 1) / BLK_PER_BATCH;

    float ls = 0.f;   // per-thread accumulation across ALL tiles
    int   lc = 0;

    // Prologue: tile 0 -> stage 0.
    fill_tile(pred, tgt, sb, 0, b, (jb) * TILE, tid);

    for (int k = 0; k < ntiles; k++) {
        const int stage = k & 1;
        if (k + 1 < ntiles) {
            fill_tile(pred, tgt, sb, stage ^ 1, b,
                      (jb + (k + 1) * BLK_PER_BATCH) * TILE, tid);
            cp_wait<1>();    // tile k complete (tile k+1 may be in flight)
        } else {
            cp_wait<0>();
        }
        __syncthreads();

        const float* buf = sbuf + stage * (TILE_BYTES / 4);
        const int p = tid * 2;

        float s0 = 0.f, s1 = 0.f;
#pragma unroll
        for (int c = 0; c < NC; c++) {
            const float2 v = *reinterpret_cast<const float2*>(buf + c * TILE + p);
            s0 += __expf(v.x);
            s1 += __expf(v.y);
        }
        const int2 tt = *reinterpret_cast<const int2*>(
            reinterpret_cast<const int*>(buf + NC * TILE) + p);
        const float l0 = __logf(s0) - buf[tt.x * TILE + p];
        const float l1 = __logf(s1) - buf[tt.y * TILE + p + 1];
        if (l0 > THRESH) { ls += l0; lc++; }
        if (l1 > THRESH) { ls += l1; lc++; }

        __syncthreads();   // everyone done reading before this stage refills
    }

    // One block reduction + one atomic pair for the whole block.
#pragma unroll
    for (int o = 16; o; o >>= 1) {
        ls += __shfl_down_sync(0xffffffffu, ls, o);
        lc += __shfl_down_sync(0xffffffffu, lc, o);
    }
    if (lane == 0) { sh_f[w] = ls; sh_i[w] = lc; }
    __syncthreads();
    if (tid == 0) {
        double S = 0.0; int Cn = 0;
#pragma unroll
        for (int i = 0; i < TPB / 32; i++) { S += (double)sh_f[i]; Cn += sh_i[i]; }
        atomicAdd(&g_sum[b], S);
        atomicAdd(&g_cnt[b], Cn);
        __threadfence();
        const unsigned int tk = atomicAdd(&g_done, 1u);
        sh_last = (tk == (unsigned)(GRID - 1)) ? 1u : 0u;
    }
    __syncthreads();
    if (!sh_last) return;

    // ---------------- finalize (last block) --------------------------------
    __threadfence();

    __shared__ unsigned int hist[256];
    __shared__ unsigned int s_prefix;
    __shared__ int          s_k;
    __shared__ double       sh_d2[TPB / 32];
    __shared__ int          sh_i2[TPB / 32];
    __shared__ double       s_acc;

    if (tid == 0) s_acc = 0.0;
    __syncthreads();

    for (int bb = 0; bb < NB; bb++) {
        const int    cnt = g_cnt[bb];
        const double sum = g_sum[bb];

        if (cnt >= NMIN) {
            if (tid == 0) s_acc += sum / (double)cnt;
            __syncthreads();
        } else {
            // Exact top-NMIN via 4-pass MSB radix select (dead on this input).
            if (tid == 0) { s_prefix = 0u; s_k = NMIN; }
            __syncthreads();
            for (int pass = 0; pass < 4; pass++) {
                const int shift = 24 - pass * 8;
                for (int i = tid; i < 256; i += TPB) hist[i] = 0u;
                __syncthreads();
                const unsigned prefix  = s_prefix;
                const unsigned mask_hi = (pass == 0) ? 0u
                                       : (0xFFFFFFFFu << (shift + 8));
                for (int i = tid; i < NPB; i += TPB) {
                    const unsigned u = __float_as_uint(pixel_loss(pred, tgt, bb, i));
                    if ((u & mask_hi) == prefix)
                        atomicAdd(&hist[(u >> shift) & 255u], 1u);
                }
                __syncthreads();
                if (tid == 0) {
                    int kk = s_k;
                    int d  = 255;
                    while (d > 0 && (int)hist[d] < kk) { kk -= (int)hist[d]; d--; }
                    s_prefix = prefix | ((unsigned)d << shift);
                    s_k      = kk;
                }
                __syncthreads();
            }
            const float pivot = __uint_as_float(s_prefix);
            double fs = 0.0; int fg = 0;
            for (int i = tid; i < NPB; i += TPB) {
                const float vv = pixel_loss(pred, tgt, bb, i);
                if (vv > pivot) { fs += (double)vv; fg++; }
            }
#pragma unroll
            for (int o = 16; o; o >>= 1) {
                fs += __shfl_down_sync(0xffffffffu, fs, o);
                fg += __shfl_down_sync(0xffffffffu, fg, o);
            }
            if (lane == 0) { sh_d2[w] = fs; sh_i2[w] = fg; }
            __syncthreads();
            if (tid == 0) {
                double S = 0.0; int G = 0;
#pragma unroll
                for (int i = 0; i < TPB / 32; i++) { S += sh_d2[i]; G += sh_i2[i]; }
                const double kept = S + (double)(NMIN - G) * (double)pivot;
                s_acc += kept / (double)NMIN;
            }
            __syncthreads();
        }
    }

    if (tid == 0) {
        out[0] = (float)(s_acc / (double)NB);
#pragma unroll
        for (int i = 0; i < NB; i++) { g_sum[i] = 0.0; g_cnt[i] = 0; }
        g_done = 0u;
        __threadfence();
    }
}

extern "C" void kernel_launch(void* const* d_in, const int* in_sizes, int n_in,
                              void* d_out, int out_size) {
    const float* pred = (const float*)d_in[0];
    const int*   tgt  = (const int*)d_in[1];
    float*       out  = (float*)d_out;

    static int smem_set = 0;
    if (!smem_set) {
        cudaFuncSetAttribute(ohem_cpa,
                             cudaFuncAttributeMaxDynamicSharedMemorySize,
                             STAGES * TILE_BYTES);
        smem_set = 1;
    }
    ohem_cpa<<<GRID, TPB, STAGES * TILE_BYTES>>>(pred, tgt, out);
}